// round 16
// baseline (speedup 1.0000x reference)
#include <cuda_runtime.h>
#include <cstdint>

#define LRELU_ALPHA 0.2f
#define LOG2E 1.4426950408889634f
#define NEG2  (-1.0e18f)

#define BATCH 8
#define NNODE 2048
#define FIN   256
#define FOUT  128

// ---------------- scratch (device globals) ----------------
static __device__ float    g_f1[BATCH * NNODE];   // f1 * log2e
static __device__ float    g_f2[BATCH * NNODE];   // f2 * log2e
// split-bf16 h: each unsigned holds 2 bf16 (cols 2k, 2k+1). Layout [b*N + j][64]
static __device__ unsigned g_hh[BATCH * NNODE * (FOUT / 2)];   // high parts
static __device__ unsigned g_hl[BATCH * NNODE * (FOUT / 2)];   // residuals

// ---------------- helpers ----------------
__device__ __forceinline__ unsigned smem_u32(const void* p) {
    unsigned a;
    asm("{ .reg .u64 t; cvta.to.shared.u64 t, %1; cvt.u32.u64 %0, t; }" : "=r"(a) : "l"(p));
    return a;
}
#define SW128(off) ((off) ^ (((off) >> 3) & 0x70))

// cvt: lo-half = a, hi-half = b
#define CVT_BF16X2(res, a, b) \
    asm("cvt.rn.satfinite.bf16x2.f32 %0, %1, %2;" : "=r"(res) : "f"(b), "f"(a))

__device__ __forceinline__ unsigned long long pk2(float a, float b) {
    unsigned long long r;
    asm("mov.b64 %0, {%1,%2};" : "=l"(r) : "f"(a), "f"(b));
    return r;
}
__device__ __forceinline__ void upk2(unsigned long long v, float& a, float& b) {
    asm("mov.b64 {%0,%1}, %2;" : "=f"(a), "=f"(b) : "l"(v));
}
__device__ __forceinline__ unsigned long long ffma2(unsigned long long a,
                                                    unsigned long long b,
                                                    unsigned long long c) {
    unsigned long long d;
    asm("fma.rn.f32x2 %0, %1, %2, %3;" : "=l"(d) : "l"(a), "l"(b), "l"(c));
    return d;
}

__device__ __forceinline__ void ldsm_x4_t(unsigned& r0, unsigned& r1, unsigned& r2,
                                          unsigned& r3, unsigned addr) {
    asm volatile("ldmatrix.sync.aligned.m8n8.x4.trans.shared.b16 {%0,%1,%2,%3}, [%4];"
                 : "=r"(r0), "=r"(r1), "=r"(r2), "=r"(r3) : "r"(addr));
}
__device__ __forceinline__ void mma_bf16(float* c, const unsigned* a,
                                         unsigned b0, unsigned b1) {
    asm volatile(
        "mma.sync.aligned.m16n8k16.row.col.f32.bf16.bf16.f32 "
        "{%0,%1,%2,%3}, {%4,%5,%6,%7}, {%8,%9}, {%0,%1,%2,%3};"
        : "+f"(c[0]), "+f"(c[1]), "+f"(c[2]), "+f"(c[3])
        : "r"(a[0]), "r"(a[1]), "r"(a[2]), "r"(a[3]), "r"(b0), "r"(b1));
}

// masked leaky-relu + exp2 (inputs pre-scaled by log2e)
__device__ __forceinline__ float pcalc(float f1, float f2, int msk) {
    float s = f1 + f2;
    float e = fmaxf(s, LRELU_ALPHA * s);
    e = msk ? e : NEG2;
    float r;
    asm("ex2.approx.f32 %0, %1;" : "=f"(r) : "f"(e));
    return r;
}

// ============================================================
// Kernel 1: h = x@W ; f1,f2 (scaled by log2e) ; write split-bf16 h
// ============================================================
__global__ void __launch_bounds__(256) k_gemm(const float* __restrict__ x,
                                              const float* __restrict__ W,
                                              const float* __restrict__ a) {
    __shared__ float xs[64][32];
    __shared__ float ws[32][128];
    const int t = threadIdx.x;
    const int row0 = blockIdx.x * 64;
    const int c4 = (t & 31) * 4;
    const int rg = t >> 5;

    unsigned long long acc[8][2];
#pragma unroll
    for (int r = 0; r < 8; r++) { acc[r][0] = 0ULL; acc[r][1] = 0ULL; }

    for (int k0 = 0; k0 < FIN; k0 += 32) {
        {
            const int rr = t >> 3, cc = (t & 7) * 4;
            float4 v0 = *reinterpret_cast<const float4*>(&x[(size_t)(row0 + rr) * FIN + k0 + cc]);
            float4 v1 = *reinterpret_cast<const float4*>(&x[(size_t)(row0 + rr + 32) * FIN + k0 + cc]);
            *reinterpret_cast<float4*>(&xs[rr][cc]) = v0;
            *reinterpret_cast<float4*>(&xs[rr + 32][cc]) = v1;
        }
        {
            const int kr = t >> 5, cc = (t & 31) * 4;
#pragma unroll
            for (int i = 0; i < 4; i++) {
                float4 v = *reinterpret_cast<const float4*>(&W[(size_t)(k0 + kr + i * 8) * FOUT + cc]);
                *reinterpret_cast<float4*>(&ws[kr + i * 8][cc]) = v;
            }
        }
        __syncthreads();
#pragma unroll
        for (int k = 0; k < 32; k++) {
            ulonglong2 wv = *reinterpret_cast<const ulonglong2*>(&ws[k][c4]);
#pragma unroll
            for (int r = 0; r < 8; r++) {
                float xv = xs[rg * 8 + r][k];
                unsigned long long xd = pk2(xv, xv);
                acc[r][0] = ffma2(xd, wv.x, acc[r][0]);
                acc[r][1] = ffma2(xd, wv.y, acc[r][1]);
            }
        }
        __syncthreads();
    }

    float4 a1 = *reinterpret_cast<const float4*>(&a[c4]);
    float4 a2 = *reinterpret_cast<const float4*>(&a[FOUT + c4]);
#pragma unroll
    for (int r = 0; r < 8; r++) {
        float h0, h1, h2, h3;
        upk2(acc[r][0], h0, h1);
        upk2(acc[r][1], h2, h3);
        const int grow = row0 + rg * 8 + r;
        unsigned hi01, hi23, lo01, lo23;
        CVT_BF16X2(hi01, h0, h1);
        CVT_BF16X2(hi23, h2, h3);
        float q0 = __uint_as_float(hi01 << 16);
        float q1 = __uint_as_float(hi01 & 0xffff0000u);
        float q2 = __uint_as_float(hi23 << 16);
        float q3 = __uint_as_float(hi23 & 0xffff0000u);
        CVT_BF16X2(lo01, h0 - q0, h1 - q1);
        CVT_BF16X2(lo23, h2 - q2, h3 - q3);
        *reinterpret_cast<uint2*>(&g_hh[(size_t)grow * 64 + (c4 >> 1)]) = make_uint2(hi01, hi23);
        *reinterpret_cast<uint2*>(&g_hl[(size_t)grow * 64 + (c4 >> 1)]) = make_uint2(lo01, lo23);

        float s1 = h0 * a1.x + h1 * a1.y + h2 * a1.z + h3 * a1.w;
        float s2 = h0 * a2.x + h1 * a2.y + h2 * a2.z + h3 * a2.w;
#pragma unroll
        for (int off = 16; off; off >>= 1) {
            s1 += __shfl_xor_sync(0xffffffffu, s1, off);
            s2 += __shfl_xor_sync(0xffffffffu, s2, off);
        }
        if ((t & 31) == 0) { g_f1[grow] = s1 * LOG2E; g_f2[grow] = s2 * LOG2E; }
    }
}

// ============================================================
// Kernel 2: HMMA fused attention. P in A-fragment registers.
// adj + f2 tiles prefetched via cp.async (double-buffered, one tile
// ahead) -> inner loop has NO global-latency dependence.
// ============================================================
#define JT2 64
#define NT2 (NNODE / JT2)            // 32

#define ADJ_STRIDE 68                 // ints; 272B row stride (16B aligned, low conflict)
#define ADJ_BUF (64 * ADJ_STRIDE * 4) // 17408 B

#define OFF_H    0                    // 2 bufs x 32 KB: [hi h0][hi h1][lo h0][lo h1]
#define OFF_ADJ  65536                // 2 bufs x 17408
#define OFF_F2   (OFF_ADJ + 2 * ADJ_BUF)      // 2 bufs x 256 B
#define OFF_LROW (OFF_F2 + 512)
#define SMEM_ATTN (OFF_LROW + 256)    // ~101.1 KB

__global__ void __launch_bounds__(256, 2) k_attn(const int* __restrict__ adj,
                                                 float* __restrict__ out) {
    extern __shared__ char smem[];
    const unsigned sb = smem_u32(smem);
    const int tid = threadIdx.x;
    const int w = tid >> 5, lane = tid & 31;
    const int b = blockIdx.y;
    const int row0 = blockIdx.x * 64;

    // ---- MMA geometry ----
    const int mrow0 = (w & 3) * 16;          // warp's m-slab (local rows)
    const int nhalf = w >> 2;                // warp's F-half (64 cols)
    const int g = lane >> 2, q = lane & 3;
    const int asub = lane >> 3, ai = lane & 7;
    const int b_krow = (asub & 1) * 8 + ai;
    const int b_nof = (asub >> 1) * 8;

    const int r0g = row0 + mrow0 + g;        // global row (fragment row 0)
    const float f1a = g_f1[b * NNODE + r0g];
    const float f1b = g_f1[b * NNODE + r0g + 8];
    const float* f2B = g_f2 + b * NNODE;
    const char* hhB = (const char*)g_hh + (size_t)(b * NNODE) * 256;
    const char* hlB = (const char*)g_hl + (size_t)(b * NNODE) * 256;
    const char* adjG = (const char*)(adj + ((size_t)(b * NNODE + row0)) * NNODE);

    float acc[8][4];
#pragma unroll
    for (int i = 0; i < 8; i++)
#pragma unroll
        for (int k = 0; k < 4; k++) acc[i][k] = 0.f;
    float lp0 = 0.f, lp1 = 0.f;

    // ---- stage H (hi+lo), adj, f2 tiles for t2 (one cp.async group) ----
    auto stage = [&](int t2) {
        const int buf = t2 & 1;
        const unsigned hb = sb + OFF_H + buf * 32768;
        const char* sh = hhB + (size_t)t2 * 64 * 256;
        const char* sl = hlB + (size_t)t2 * 64 * 256;
#pragma unroll
        for (int k = 0; k < 4; k++) {
            int idx = tid * 4 + k;           // 0..1023
            int row = idx >> 4, ch = idx & 15;
            int half = ch >> 3, c = ch & 7;
            unsigned swo = SW128((unsigned)(row * 128 + c * 16));
            unsigned dh = hb + half * 8192 + swo;
            unsigned dl = hb + 16384 + half * 8192 + swo;
            const char* gsrc = sh + row * 256 + half * 128 + c * 16;
            asm volatile("cp.async.cg.shared.global [%0], [%1], 16;" :: "r"(dh), "l"(gsrc));
            gsrc = sl + row * 256 + half * 128 + c * 16;
            asm volatile("cp.async.cg.shared.global [%0], [%1], 16;" :: "r"(dl), "l"(gsrc));
        }
        // adj tile: 64 rows x 256B -> padded rows of 272B
        const unsigned ab = sb + OFF_ADJ + buf * ADJ_BUF;
        const char* asrc = adjG + (size_t)t2 * 64 * 4;
#pragma unroll
        for (int k = 0; k < 4; k++) {
            int c = tid * 4 + k;             // 0..1023
            int row = c >> 4, ci = c & 15;
            unsigned d = ab + (unsigned)(row * (ADJ_STRIDE * 4) + ci * 16);
            asm volatile("cp.async.cg.shared.global [%0], [%1], 16;"
                         :: "r"(d), "l"(asrc + (size_t)row * (NNODE * 4) + ci * 16));
        }
        // f2 tile: 64 floats
        if (tid < 16) {
            unsigned d = sb + OFF_F2 + buf * 256 + tid * 16;
            asm volatile("cp.async.cg.shared.global [%0], [%1], 16;"
                         :: "r"(d), "l"((const char*)(f2B + t2 * 64) + tid * 16));
        }
        asm volatile("cp.async.commit_group;");
    };

    stage(0);

    for (int t = 0; t < NT2; t++) {
        __syncthreads();                       // old bufs fully consumed
        if (t + 1 < NT2) {
            stage(t + 1);
            asm volatile("cp.async.wait_group 1;");   // tile-t group resident
        } else {
            asm volatile("cp.async.wait_group 0;");
        }
        __syncthreads();                              // visible to all warps

        const int buf = t & 1;
        const unsigned hb = sb + OFF_H + buf * 32768 + nhalf * 8192;
        const int* r0p = (const int*)(smem + OFF_ADJ + buf * ADJ_BUF) +
                         (mrow0 + g) * ADJ_STRIDE;
        const int* r1p = r0p + 8 * ADJ_STRIDE;
        const float* f2T = (const float*)(smem + OFF_F2 + buf * 256);

#pragma unroll
        for (int ks = 0; ks < 4; ks++) {
            const int jb = ks * 16 + q * 2;
            uint2 avA0 = *reinterpret_cast<const uint2*>(r0p + jb);
            uint2 avA1 = *reinterpret_cast<const uint2*>(r0p + jb + 8);
            uint2 avB0 = *reinterpret_cast<const uint2*>(r1p + jb);
            uint2 avB1 = *reinterpret_cast<const uint2*>(r1p + jb + 8);
            float2 f20 = *reinterpret_cast<const float2*>(f2T + jb);
            float2 f21 = *reinterpret_cast<const float2*>(f2T + jb + 8);

            float p0 = pcalc(f1a, f20.x, avA0.x);
            float p1 = pcalc(f1a, f20.y, avA0.y);
            float p2 = pcalc(f1b, f20.x, avB0.x);
            float p3 = pcalc(f1b, f20.y, avB0.y);
            float p4 = pcalc(f1a, f21.x, avA1.x);
            float p5 = pcalc(f1a, f21.y, avA1.y);
            float p6 = pcalc(f1b, f21.x, avB1.x);
            float p7 = pcalc(f1b, f21.y, avB1.y);
            if (nhalf == 0) {
                lp0 += (p0 + p1) + (p4 + p5);
                lp1 += (p2 + p3) + (p6 + p7);
            }
            unsigned PAh[4], PAl[4];
            CVT_BF16X2(PAh[0], p0, p1);
            CVT_BF16X2(PAh[1], p2, p3);
            CVT_BF16X2(PAh[2], p4, p5);
            CVT_BF16X2(PAh[3], p6, p7);
            {
                float qa, qb;
                qa = __uint_as_float(PAh[0] << 16);
                qb = __uint_as_float(PAh[0] & 0xffff0000u);
                CVT_BF16X2(PAl[0], p0 - qa, p1 - qb);
                qa = __uint_as_float(PAh[1] << 16);
                qb = __uint_as_float(PAh[1] & 0xffff0000u);
                CVT_BF16X2(PAl[1], p2 - qa, p3 - qb);
                qa = __uint_as_float(PAh[2] << 16);
                qb = __uint_as_float(PAh[2] & 0xffff0000u);
                CVT_BF16X2(PAl[2], p4 - qa, p5 - qb);
                qa = __uint_as_float(PAh[3] << 16);
                qb = __uint_as_float(PAh[3] & 0xffff0000u);
                CVT_BF16X2(PAl[3], p6 - qa, p7 - qb);
            }
#pragma unroll
            for (int nb = 0; nb < 4; nb++) {
                unsigned Bh[4], Bl[4];
                unsigned off = SW128(
                    (unsigned)((ks * 16 + b_krow) * 128 + (nb * 16 + b_nof) * 2));
                ldsm_x4_t(Bh[0], Bh[1], Bh[2], Bh[3], hb + off);
                ldsm_x4_t(Bl[0], Bl[1], Bl[2], Bl[3], hb + 16384 + off);
                mma_bf16(acc[nb * 2],     PAh, Bh[0], Bh[1]);
                mma_bf16(acc[nb * 2 + 1], PAh, Bh[2], Bh[3]);
                mma_bf16(acc[nb * 2],     PAh, Bl[0], Bl[1]);
                mma_bf16(acc[nb * 2 + 1], PAh, Bl[2], Bl[3]);
                mma_bf16(acc[nb * 2],     PAl, Bh[0], Bh[1]);
                mma_bf16(acc[nb * 2 + 1], PAl, Bh[2], Bh[3]);
            }
        }
    }

    // ---- row sums: reduce within quad (lanes share row), publish ----
    if (nhalf == 0) {
#pragma unroll
        for (int off = 1; off <= 2; off <<= 1) {
            lp0 += __shfl_xor_sync(0xffffffffu, lp0, off);
            lp1 += __shfl_xor_sync(0xffffffffu, lp1, off);
        }
        if (q == 0) {
            reinterpret_cast<float*>(smem + OFF_LROW)[mrow0 + g] = lp0;
            reinterpret_cast<float*>(smem + OFF_LROW)[mrow0 + g + 8] = lp1;
        }
    }
    __syncthreads();

    // ---- epilogue: normalize + ELU + store ----
    const float inv0 = 1.0f / reinterpret_cast<float*>(smem + OFF_LROW)[mrow0 + g];
    const float inv1 = 1.0f / reinterpret_cast<float*>(smem + OFF_LROW)[mrow0 + g + 8];
    float* outB = out + ((size_t)(b * NNODE + row0)) * FOUT;
#pragma unroll
    for (int k = 0; k < 8; k++) {
        const int col = nhalf * 64 + (k >> 1) * 16 + (k & 1) * 8 + q * 2;
        float v0 = acc[k][0] * inv0, v1 = acc[k][1] * inv0;
        float v2 = acc[k][2] * inv1, v3 = acc[k][3] * inv1;
        v0 = v0 > 0.f ? v0 : expm1f(v0);
        v1 = v1 > 0.f ? v1 : expm1f(v1);
        v2 = v2 > 0.f ? v2 : expm1f(v2);
        v3 = v3 > 0.f ? v3 : expm1f(v3);
        *reinterpret_cast<float2*>(&outB[(size_t)(mrow0 + g) * FOUT + col]) =
            make_float2(v0, v1);
        *reinterpret_cast<float2*>(&outB[(size_t)(mrow0 + g + 8) * FOUT + col]) =
            make_float2(v2, v3);
    }
}

// ============================================================
extern "C" void kernel_launch(void* const* d_in, const int* in_sizes, int n_in,
                              void* d_out, int out_size) {
    const float* x   = (const float*)d_in[0];   // (8, 2048, 256) f32
    const int*   adj = (const int*)d_in[1];     // (8, 2048, 2048) i32
    const float* W   = (const float*)d_in[2];   // (256, 128) f32
    const float* a   = (const float*)d_in[3];   // (256, 1) f32
    float* out = (float*)d_out;                 // (8, 2048, 128) f32

    cudaFuncSetAttribute(k_attn, cudaFuncAttributeMaxDynamicSharedMemorySize, SMEM_ATTN);

    k_gemm<<<(BATCH * NNODE) / 64, 256>>>(x, W, a);
    dim3 grid(NNODE / 64, BATCH);
    k_attn<<<grid, 256, SMEM_ATTN>>>(adj, out);
}

// round 17
// speedup vs baseline: 1.0668x; 1.0668x over previous
#include <cuda_runtime.h>
#include <cstdint>

#define LRELU_ALPHA 0.2f
#define LOG2E 1.4426950408889634f
#define NEG2  (-1.0e18f)

#define BATCH 8
#define NNODE 2048
#define FIN   256
#define FOUT  128

// ---------------- scratch (device globals) ----------------
static __device__ float    g_f1[BATCH * NNODE];   // f1 * log2e
static __device__ float    g_f2[BATCH * NNODE];   // f2 * log2e
// split-bf16 h: each unsigned holds 2 bf16 (cols 2k, 2k+1). Layout [b*N + j][64]
static __device__ unsigned g_hh[BATCH * NNODE * (FOUT / 2)];   // high parts
static __device__ unsigned g_hl[BATCH * NNODE * (FOUT / 2)];   // residuals

// ---------------- helpers ----------------
__device__ __forceinline__ unsigned smem_u32(const void* p) {
    unsigned a;
    asm("{ .reg .u64 t; cvta.to.shared.u64 t, %1; cvt.u32.u64 %0, t; }" : "=r"(a) : "l"(p));
    return a;
}
#define SW128(off) ((off) ^ (((off) >> 3) & 0x70))

// cvt: lo-half = a, hi-half = b
#define CVT_BF16X2(res, a, b) \
    asm("cvt.rn.satfinite.bf16x2.f32 %0, %1, %2;" : "=r"(res) : "f"(b), "f"(a))

__device__ __forceinline__ unsigned long long pk2(float a, float b) {
    unsigned long long r;
    asm("mov.b64 %0, {%1,%2};" : "=l"(r) : "f"(a), "f"(b));
    return r;
}
__device__ __forceinline__ void upk2(unsigned long long v, float& a, float& b) {
    asm("mov.b64 {%0,%1}, %2;" : "=f"(a), "=f"(b) : "l"(v));
}
__device__ __forceinline__ unsigned long long ffma2(unsigned long long a,
                                                    unsigned long long b,
                                                    unsigned long long c) {
    unsigned long long d;
    asm("fma.rn.f32x2 %0, %1, %2, %3;" : "=l"(d) : "l"(a), "l"(b), "l"(c));
    return d;
}

__device__ __forceinline__ void ldsm_x4_t(unsigned& r0, unsigned& r1, unsigned& r2,
                                          unsigned& r3, unsigned addr) {
    asm volatile("ldmatrix.sync.aligned.m8n8.x4.trans.shared.b16 {%0,%1,%2,%3}, [%4];"
                 : "=r"(r0), "=r"(r1), "=r"(r2), "=r"(r3) : "r"(addr));
}
__device__ __forceinline__ void mma_bf16(float* c, const unsigned* a,
                                         unsigned b0, unsigned b1) {
    asm volatile(
        "mma.sync.aligned.m16n8k16.row.col.f32.bf16.bf16.f32 "
        "{%0,%1,%2,%3}, {%4,%5,%6,%7}, {%8,%9}, {%0,%1,%2,%3};"
        : "+f"(c[0]), "+f"(c[1]), "+f"(c[2]), "+f"(c[3])
        : "r"(a[0]), "r"(a[1]), "r"(a[2]), "r"(a[3]), "r"(b0), "r"(b1));
}

// masked leaky-relu + exp2 (inputs pre-scaled by log2e)
__device__ __forceinline__ float pcalc(float f1, float f2, int msk) {
    float s = f1 + f2;
    float e = fmaxf(s, LRELU_ALPHA * s);
    e = msk ? e : NEG2;
    float r;
    asm("ex2.approx.f32 %0, %1;" : "=f"(r) : "f"(e));
    return r;
}

// ============================================================
// Kernel 1: h = x@W ; f1,f2 (scaled by log2e) ; write split-bf16 h
// ============================================================
__global__ void __launch_bounds__(256) k_gemm(const float* __restrict__ x,
                                              const float* __restrict__ W,
                                              const float* __restrict__ a) {
    __shared__ float xs[64][32];
    __shared__ float ws[32][128];
    const int t = threadIdx.x;
    const int row0 = blockIdx.x * 64;
    const int c4 = (t & 31) * 4;
    const int rg = t >> 5;

    unsigned long long acc[8][2];
#pragma unroll
    for (int r = 0; r < 8; r++) { acc[r][0] = 0ULL; acc[r][1] = 0ULL; }

    for (int k0 = 0; k0 < FIN; k0 += 32) {
        {
            const int rr = t >> 3, cc = (t & 7) * 4;
            float4 v0 = *reinterpret_cast<const float4*>(&x[(size_t)(row0 + rr) * FIN + k0 + cc]);
            float4 v1 = *reinterpret_cast<const float4*>(&x[(size_t)(row0 + rr + 32) * FIN + k0 + cc]);
            *reinterpret_cast<float4*>(&xs[rr][cc]) = v0;
            *reinterpret_cast<float4*>(&xs[rr + 32][cc]) = v1;
        }
        {
            const int kr = t >> 5, cc = (t & 31) * 4;
#pragma unroll
            for (int i = 0; i < 4; i++) {
                float4 v = *reinterpret_cast<const float4*>(&W[(size_t)(k0 + kr + i * 8) * FOUT + cc]);
                *reinterpret_cast<float4*>(&ws[kr + i * 8][cc]) = v;
            }
        }
        __syncthreads();
#pragma unroll
        for (int k = 0; k < 32; k++) {
            ulonglong2 wv = *reinterpret_cast<const ulonglong2*>(&ws[k][c4]);
#pragma unroll
            for (int r = 0; r < 8; r++) {
                float xv = xs[rg * 8 + r][k];
                unsigned long long xd = pk2(xv, xv);
                acc[r][0] = ffma2(xd, wv.x, acc[r][0]);
                acc[r][1] = ffma2(xd, wv.y, acc[r][1]);
            }
        }
        __syncthreads();
    }

    float4 a1 = *reinterpret_cast<const float4*>(&a[c4]);
    float4 a2 = *reinterpret_cast<const float4*>(&a[FOUT + c4]);
#pragma unroll
    for (int r = 0; r < 8; r++) {
        float h0, h1, h2, h3;
        upk2(acc[r][0], h0, h1);
        upk2(acc[r][1], h2, h3);
        const int grow = row0 + rg * 8 + r;
        unsigned hi01, hi23, lo01, lo23;
        CVT_BF16X2(hi01, h0, h1);
        CVT_BF16X2(hi23, h2, h3);
        float q0 = __uint_as_float(hi01 << 16);
        float q1 = __uint_as_float(hi01 & 0xffff0000u);
        float q2 = __uint_as_float(hi23 << 16);
        float q3 = __uint_as_float(hi23 & 0xffff0000u);
        CVT_BF16X2(lo01, h0 - q0, h1 - q1);
        CVT_BF16X2(lo23, h2 - q2, h3 - q3);
        *reinterpret_cast<uint2*>(&g_hh[(size_t)grow * 64 + (c4 >> 1)]) = make_uint2(hi01, hi23);
        *reinterpret_cast<uint2*>(&g_hl[(size_t)grow * 64 + (c4 >> 1)]) = make_uint2(lo01, lo23);

        float s1 = h0 * a1.x + h1 * a1.y + h2 * a1.z + h3 * a1.w;
        float s2 = h0 * a2.x + h1 * a2.y + h2 * a2.z + h3 * a2.w;
#pragma unroll
        for (int off = 16; off; off >>= 1) {
            s1 += __shfl_xor_sync(0xffffffffu, s1, off);
            s2 += __shfl_xor_sync(0xffffffffu, s2, off);
        }
        if ((t & 31) == 0) { g_f1[grow] = s1 * LOG2E; g_f2[grow] = s2 * LOG2E; }
    }
}

// ============================================================
// Kernel 2: HMMA fused attention with PAIR-DEDUPED P generation.
// Warp pair (w, w+4) shares m-rows; each warp computes A-fragments for
// only 2 of 4 k-steps (its nhalf), exchanged via double-buffered smem
// (uint4, conflict-free). P-gen for tile t+1 runs after MMA(t).
// adj/f2 prefetched into regs a tile ahead (R9 timing, no adj smem).
// ============================================================
#define JT2 64
#define NT2 (NNODE / JT2)            // 32

#define OFF_H    0                    // 2 bufs x 32 KB: [hi h0][hi h1][lo h0][lo h1]
#define OFF_EXH  65536                // 2 bufs x 8 KB: PAh frags
#define OFF_EXL  (OFF_EXH + 16384)    // 2 bufs x 8 KB: PAl frags
#define OFF_LROW (OFF_EXL + 16384)    // 2 x 64 floats
#define SMEM_ATTN (OFF_LROW + 512)    // 98.8 KB

__global__ void __launch_bounds__(256, 2) k_attn(const int* __restrict__ adj,
                                                 float* __restrict__ out) {
    extern __shared__ char smem[];
    const unsigned sb = smem_u32(smem);
    const int tid = threadIdx.x;
    const int w = tid >> 5, lane = tid & 31;
    const int b = blockIdx.y;
    const int row0 = blockIdx.x * 64;

    // ---- MMA geometry ----
    const int pair = w & 3;                  // warp-pair id (shares m-slab)
    const int mrow0 = pair * 16;             // warp's m-slab (local rows)
    const int nhalf = w >> 2;                // warp's F-half (64 cols)
    const int g = lane >> 2, q = lane & 3;
    const int asub = lane >> 3, ai = lane & 7;
    const int b_krow = (asub & 1) * 8 + ai;
    const int b_nof = (asub >> 1) * 8;

    const int r0g = row0 + mrow0 + g;        // global row (fragment row 0)
    const float f1a = g_f1[b * NNODE + r0g];
    const float f1b = g_f1[b * NNODE + r0g + 8];
    const float* f2B = g_f2 + b * NNODE;
    const char* hhB = (const char*)g_hh + (size_t)(b * NNODE) * 256;
    const char* hlB = (const char*)g_hl + (size_t)(b * NNODE) * 256;
    const int* adjR0 = adj + ((size_t)(b * NNODE + r0g)) * NNODE;
    const int* adjR1 = adjR0 + (size_t)8 * NNODE;

    // exchange slot base for this thread (16B stride, conflict-free .128)
    const unsigned exslot = (unsigned)((pair * 4) * 32 + lane) * 16;

    float acc[8][4];
#pragma unroll
    for (int i = 0; i < 8; i++)
#pragma unroll
        for (int k = 0; k < 4; k++) acc[i][k] = 0.f;
    float lp0 = 0.f, lp1 = 0.f;

    // adj/f2 prefetch registers for this warp's 2 k-steps
    uint2  avA[2][2], avB[2][2];
    float2 fC[2][2];

    // ---- stage H (hi+lo) tile ----
    auto stage = [&](int t2) {
        const unsigned hb = sb + OFF_H + (t2 & 1) * 32768;
        const char* sh = hhB + (size_t)t2 * 64 * 256;
        const char* sl = hlB + (size_t)t2 * 64 * 256;
#pragma unroll
        for (int k = 0; k < 4; k++) {
            int idx = tid * 4 + k;           // 0..1023
            int row = idx >> 4, ch = idx & 15;
            int half = ch >> 3, c = ch & 7;
            unsigned swo = SW128((unsigned)(row * 128 + c * 16));
            unsigned dh = hb + half * 8192 + swo;
            unsigned dl = hb + 16384 + half * 8192 + swo;
            const char* gsrc = sh + row * 256 + half * 128 + c * 16;
            asm volatile("cp.async.cg.shared.global [%0], [%1], 16;" :: "r"(dh), "l"(gsrc));
            gsrc = sl + row * 256 + half * 128 + c * 16;
            asm volatile("cp.async.cg.shared.global [%0], [%1], 16;" :: "r"(dl), "l"(gsrc));
        }
        asm volatile("cp.async.commit_group;");
    };

    // ---- load adj/f2 regs for tile t2, this warp's 2 ks ----
    auto pload = [&](int t2) {
#pragma unroll
        for (int kk = 0; kk < 2; kk++) {
            const int ks = nhalf * 2 + kk;
            const int jb = t2 * JT2 + ks * 16 + q * 2;
            avA[kk][0] = *reinterpret_cast<const uint2*>(adjR0 + jb);
            avA[kk][1] = *reinterpret_cast<const uint2*>(adjR0 + jb + 8);
            avB[kk][0] = *reinterpret_cast<const uint2*>(adjR1 + jb);
            avB[kk][1] = *reinterpret_cast<const uint2*>(adjR1 + jb + 8);
            fC[kk][0] = *reinterpret_cast<const float2*>(f2B + jb);
            fC[kk][1] = *reinterpret_cast<const float2*>(f2B + jb + 8);
        }
    };

    // ---- exp + split + store A-fragments for tile t2 (own 2 ks) ----
    auto pstore = [&](int t2) {
        const unsigned ebh = sb + OFF_EXH + (t2 & 1) * 8192 + exslot;
        const unsigned ebl = sb + OFF_EXL + (t2 & 1) * 8192 + exslot;
#pragma unroll
        for (int kk = 0; kk < 2; kk++) {
            const int ks = nhalf * 2 + kk;
            float p0 = pcalc(f1a, fC[kk][0].x, avA[kk][0].x);
            float p1 = pcalc(f1a, fC[kk][0].y, avA[kk][0].y);
            float p2 = pcalc(f1b, fC[kk][0].x, avB[kk][0].x);
            float p3 = pcalc(f1b, fC[kk][0].y, avB[kk][0].y);
            float p4 = pcalc(f1a, fC[kk][1].x, avA[kk][1].x);
            float p5 = pcalc(f1a, fC[kk][1].y, avA[kk][1].y);
            float p6 = pcalc(f1b, fC[kk][1].x, avB[kk][1].x);
            float p7 = pcalc(f1b, fC[kk][1].y, avB[kk][1].y);
            lp0 += (p0 + p1) + (p4 + p5);
            lp1 += (p2 + p3) + (p6 + p7);
            unsigned h0, h1, h2, h3, l0, l1, l2, l3;
            CVT_BF16X2(h0, p0, p1);
            CVT_BF16X2(h1, p2, p3);
            CVT_BF16X2(h2, p4, p5);
            CVT_BF16X2(h3, p6, p7);
            float qa, qb;
            qa = __uint_as_float(h0 << 16);
            qb = __uint_as_float(h0 & 0xffff0000u);
            CVT_BF16X2(l0, p0 - qa, p1 - qb);
            qa = __uint_as_float(h1 << 16);
            qb = __uint_as_float(h1 & 0xffff0000u);
            CVT_BF16X2(l1, p2 - qa, p3 - qb);
            qa = __uint_as_float(h2 << 16);
            qb = __uint_as_float(h2 & 0xffff0000u);
            CVT_BF16X2(l2, p4 - qa, p5 - qb);
            qa = __uint_as_float(h3 << 16);
            qb = __uint_as_float(h3 & 0xffff0000u);
            CVT_BF16X2(l3, p6 - qa, p7 - qb);
            asm volatile("st.shared.v4.b32 [%0], {%1,%2,%3,%4};"
                         :: "r"(ebh + (unsigned)ks * 512), "r"(h0), "r"(h1), "r"(h2), "r"(h3)
                         : "memory");
            asm volatile("st.shared.v4.b32 [%0], {%1,%2,%3,%4};"
                         :: "r"(ebl + (unsigned)ks * 512), "r"(l0), "r"(l1), "r"(l2), "r"(l3)
                         : "memory");
        }
    };

    // prologue
    stage(0);
    pload(0);
    pstore(0);

    for (int t = 0; t < NT2; t++) {
        __syncthreads();                       // old H buf + old exch consumed
        if (t + 1 < NT2) {
            stage(t + 1);
            pload(t + 1);                      // adj/f2 DRAM loads in flight
            asm volatile("cp.async.wait_group 1;");   // H(t) resident
        } else {
            asm volatile("cp.async.wait_group 0;");
        }
        __syncthreads();                       // H(t) + exch(t) visible

        const unsigned hb = sb + OFF_H + (t & 1) * 32768 + nhalf * 8192;
        const unsigned ebh = sb + OFF_EXH + (t & 1) * 8192 + exslot;
        const unsigned ebl = sb + OFF_EXL + (t & 1) * 8192 + exslot;
#pragma unroll
        for (int ks = 0; ks < 4; ks++) {
            unsigned PAh[4], PAl[4];
            asm volatile("ld.shared.v4.b32 {%0,%1,%2,%3}, [%4];"
                         : "=r"(PAh[0]), "=r"(PAh[1]), "=r"(PAh[2]), "=r"(PAh[3])
                         : "r"(ebh + (unsigned)ks * 512));
            asm volatile("ld.shared.v4.b32 {%0,%1,%2,%3}, [%4];"
                         : "=r"(PAl[0]), "=r"(PAl[1]), "=r"(PAl[2]), "=r"(PAl[3])
                         : "r"(ebl + (unsigned)ks * 512));
#pragma unroll
            for (int nb = 0; nb < 4; nb++) {
                unsigned Bh[4], Bl[4];
                unsigned off = SW128(
                    (unsigned)((ks * 16 + b_krow) * 128 + (nb * 16 + b_nof) * 2));
                ldsm_x4_t(Bh[0], Bh[1], Bh[2], Bh[3], hb + off);
                ldsm_x4_t(Bl[0], Bl[1], Bl[2], Bl[3], hb + 16384 + off);
                mma_bf16(acc[nb * 2],     PAh, Bh[0], Bh[1]);
                mma_bf16(acc[nb * 2 + 1], PAh, Bh[2], Bh[3]);
                mma_bf16(acc[nb * 2],     PAh, Bl[0], Bl[1]);
                mma_bf16(acc[nb * 2 + 1], PAh, Bl[2], Bl[3]);
                mma_bf16(acc[nb * 2],     PAl, Bh[0], Bh[1]);
                mma_bf16(acc[nb * 2 + 1], PAl, Bh[2], Bh[3]);
            }
        }

        if (t + 1 < NT2) pstore(t + 1);        // exp+split into other exch buf
    }

    // ---- row sums: quad-reduce, publish per-nhalf partials ----
#pragma unroll
    for (int off = 1; off <= 2; off <<= 1) {
        lp0 += __shfl_xor_sync(0xffffffffu, lp0, off);
        lp1 += __shfl_xor_sync(0xffffffffu, lp1, off);
    }
    if (q == 0) {
        reinterpret_cast<float*>(smem + OFF_LROW)[nhalf * 64 + mrow0 + g] = lp0;
        reinterpret_cast<float*>(smem + OFF_LROW)[nhalf * 64 + mrow0 + g + 8] = lp1;
    }
    __syncthreads();

    // ---- epilogue: normalize + ELU + store ----
    const float* lrow = reinterpret_cast<const float*>(smem + OFF_LROW);
    const float inv0 = 1.0f / (lrow[mrow0 + g] + lrow[64 + mrow0 + g]);
    const float inv1 = 1.0f / (lrow[mrow0 + g + 8] + lrow[64 + mrow0 + g + 8]);
    float* outB = out + ((size_t)(b * NNODE + row0)) * FOUT;
#pragma unroll
    for (int k = 0; k < 8; k++) {
        const int col = nhalf * 64 + (k >> 1) * 16 + (k & 1) * 8 + q * 2;
        float v0 = acc[k][0] * inv0, v1 = acc[k][1] * inv0;
        float v2 = acc[k][2] * inv1, v3 = acc[k][3] * inv1;
        v0 = v0 > 0.f ? v0 : expm1f(v0);
        v1 = v1 > 0.f ? v1 : expm1f(v1);
        v2 = v2 > 0.f ? v2 : expm1f(v2);
        v3 = v3 > 0.f ? v3 : expm1f(v3);
        *reinterpret_cast<float2*>(&outB[(size_t)(mrow0 + g) * FOUT + col]) =
            make_float2(v0, v1);
        *reinterpret_cast<float2*>(&outB[(size_t)(mrow0 + g + 8) * FOUT + col]) =
            make_float2(v2, v3);
    }
}

// ============================================================
extern "C" void kernel_launch(void* const* d_in, const int* in_sizes, int n_in,
                              void* d_out, int out_size) {
    const float* x   = (const float*)d_in[0];   // (8, 2048, 256) f32
    const int*   adj = (const int*)d_in[1];     // (8, 2048, 2048) i32
    const float* W   = (const float*)d_in[2];   // (256, 128) f32
    const float* a   = (const float*)d_in[3];   // (256, 1) f32
    float* out = (float*)d_out;                 // (8, 2048, 128) f32

    cudaFuncSetAttribute(k_attn, cudaFuncAttributeMaxDynamicSharedMemorySize, SMEM_ATTN);

    k_gemm<<<(BATCH * NNODE) / 64, 256>>>(x, W, a);
    dim3 grid(NNODE / 64, BATCH);
    k_attn<<<grid, 256, SMEM_ATTN>>>(adj, out);
}